// round 5
// baseline (speedup 1.0000x reference)
#include <cuda_runtime.h>
#include <cuda_fp16.h>
#include <math.h>

// ---- persistent device state (no allocations allowed) ----
__device__ double   g_sum_d;
__device__ double   g_sum_d2;
__device__ double   g_sum_p;
__device__ unsigned g_count;    // grid-barrier arrive counter
__device__ unsigned g_gen;      // grid-barrier generation (monotonic across replays)

#define NBLK   148
#define NTHR   1024
#define NWARPS (NTHR / 32)

#define FB_BLOCKS  2048
#define FB_THREADS 256
#define FB_WARPS   (FB_THREADS / 32)

struct __align__(8) h2x2 { __half2 a, b; };

__device__ __forceinline__ float warp_reduce_f(float v) {
    #pragma unroll
    for (int o = 16; o > 0; o >>= 1)
        v += __shfl_xor_sync(0xFFFFFFFFu, v, o);
    return v;
}

// 1 - erf(x), x >= 0. Abramowitz & Stegun 7.1.26, |err| <= 1.5e-7.
__device__ __forceinline__ float one_minus_erf(float x) {
    float t = __fdividef(1.0f, fmaf(0.3275911f, x, 1.0f));
    float poly = fmaf(t, 1.061405429f, -1.453152027f);
    poly = fmaf(poly, t, 1.421413741f);
    poly = fmaf(poly, t, -0.284496736f);
    poly = fmaf(poly, t, 0.254829592f);
    poly *= t;
    return poly * __expf(-x * x);
}

template <int WARPS>
__device__ __forceinline__ void block_reduce_2(float sd, float sd2,
                                               double* out_a, double* out_b) {
    sd  = warp_reduce_f(sd);
    sd2 = warp_reduce_f(sd2);
    __shared__ double shA[WARPS];
    __shared__ double shB[WARPS];
    int lane = threadIdx.x & 31;
    int wid  = threadIdx.x >> 5;
    if (lane == 0) { shA[wid] = (double)sd; shB[wid] = (double)sd2; }
    __syncthreads();
    if (wid == 0) {
        double a = (lane < WARPS) ? shA[lane] : 0.0;
        double b = (lane < WARPS) ? shB[lane] : 0.0;
        #pragma unroll
        for (int o = 16; o > 0; o >>= 1) {
            a += __shfl_xor_sync(0xFFFFFFFFu, a, o);
            b += __shfl_xor_sync(0xFFFFFFFFu, b, o);
        }
        if (lane == 0) { atomicAdd(out_a, a); atomicAdd(out_b, b); }
    }
    __syncthreads();
}

template <int WARPS>
__device__ __forceinline__ void block_reduce_1(float s, double* out) {
    s = warp_reduce_f(s);
    __shared__ double shC[WARPS];
    int lane = threadIdx.x & 31;
    int wid  = threadIdx.x >> 5;
    if (lane == 0) shC[wid] = (double)s;
    __syncthreads();
    if (wid == 0) {
        double a = (lane < WARPS) ? shC[lane] : 0.0;
        #pragma unroll
        for (int o = 16; o > 0; o >>= 1)
            a += __shfl_xor_sync(0xFFFFFFFFu, a, o);
        if (lane == 0) atomicAdd(out, a);
    }
}

// Sense-reversing grid barrier; all 148 blocks co-resident (1 per SM).
__device__ __forceinline__ void grid_barrier(unsigned nblocks) {
    __syncthreads();
    if (threadIdx.x == 0) {
        unsigned gen = *((volatile unsigned*)&g_gen);
        __threadfence();
        unsigned arrived = atomicAdd(&g_count, 1u);
        if (arrived == nblocks - 1) {
            g_count = 0;
            __threadfence();
            atomicAdd(&g_gen, 1u);
        } else {
            while (*((volatile unsigned*)&g_gen) == gen) { }
            __threadfence();
        }
    }
    __syncthreads();
}

// ============================ fused persistent kernel =======================
extern __shared__ __half s_d[];

__global__ __launch_bounds__(NTHR, 1)
void afl_fused_kernel(const float* __restrict__ pred,
                      const float* __restrict__ target,
                      float* __restrict__ out,
                      long long n, long long chunk /* multiple of 4 */) {
    const int tid = threadIdx.x;
    const int bid = blockIdx.x;

    long long bstart = (long long)bid * chunk;
    if (bstart > n) bstart = n;
    long long bend = bstart + chunk;
    if (bend > n) bend = n;

    const long long b4s = bstart >> 2;
    const long long b4e = bend >> 2;

    const float4* __restrict__ p4 = (const float4*)pred;
    const float4* __restrict__ t4 = (const float4*)target;
    h2x2* __restrict__ s4 = (h2x2*)s_d;

    // -------- pass 1: unroll-4, front-batched streaming loads ---------------
    float sd = 0.0f, sd2 = 0.0f;
    long long i = b4s + tid;
    for (; i + 3LL * NTHR < b4e; i += 4LL * NTHR) {
        float4 av[4], bv[4];
        #pragma unroll
        for (int u = 0; u < 4; u++) av[u] = __ldcs(&p4[i + (long long)u * NTHR]);
        #pragma unroll
        for (int u = 0; u < 4; u++) bv[u] = __ldcs(&t4[i + (long long)u * NTHR]);
        #pragma unroll
        for (int u = 0; u < 4; u++) {
            float d0 = fabsf(av[u].x - bv[u].x);
            float d1 = fabsf(av[u].y - bv[u].y);
            float d2 = fabsf(av[u].z - bv[u].z);
            float d3 = fabsf(av[u].w - bv[u].w);
            sd  += (d0 + d1) + (d2 + d3);
            sd2 += fmaf(d0, d0, d1 * d1) + fmaf(d2, d2, d3 * d3);
            h2x2 pk;
            pk.a = __floats2half2_rn(d0, d1);
            pk.b = __floats2half2_rn(d2, d3);
            s4[i - b4s + (long long)u * NTHR] = pk;
        }
    }
    for (; i < b4e; i += NTHR) {
        float4 a = __ldcs(&p4[i]);
        float4 b = __ldcs(&t4[i]);
        float d0 = fabsf(a.x - b.x);
        float d1 = fabsf(a.y - b.y);
        float d2 = fabsf(a.z - b.z);
        float d3 = fabsf(a.w - b.w);
        sd  += (d0 + d1) + (d2 + d3);
        sd2 += fmaf(d0, d0, d1 * d1) + fmaf(d2, d2, d3 * d3);
        h2x2 pk;
        pk.a = __floats2half2_rn(d0, d1);
        pk.b = __floats2half2_rn(d2, d3);
        s4[i - b4s] = pk;
    }
    for (long long j = (b4e << 2) + tid; j < bend; j += NTHR) {  // n%4 tail
        float d = fabsf(pred[j] - target[j]);
        sd += d; sd2 += d * d;
        s_d[j - bstart] = __float2half_rn(d);
    }

    block_reduce_2<NWARPS>(sd, sd2, &g_sum_d, &g_sum_d2);
    __threadfence();
    grid_barrier(gridDim.x);

    // -------- var is now global-complete --------
    const double sdt  = g_sum_d;
    const double sd2t = g_sum_d2;
    const double dn   = (double)n;
    const double var  = (sd2t - sdt * sdt / dn) / (dn - 1.0);
    const float  c    = (float)(0.7071067811865476 / var);

    // -------- pass 2: unroll-4 batched LDS --------
    const long long mloc = bend - bstart;
    const long long m4   = mloc >> 2;
    float sp = 0.0f;
    long long k = tid;
    for (; k + 3LL * NTHR < m4; k += 4LL * NTHR) {
        h2x2 q[4];
        #pragma unroll
        for (int u = 0; u < 4; u++) q[u] = s4[k + (long long)u * NTHR];
        #pragma unroll
        for (int u = 0; u < 4; u++) {
            float2 f0 = __half22float2(q[u].a);
            float2 f1 = __half22float2(q[u].b);
            sp += one_minus_erf(f0.x * c) + one_minus_erf(f0.y * c);
            sp += one_minus_erf(f1.x * c) + one_minus_erf(f1.y * c);
        }
    }
    for (; k < m4; k += NTHR) {
        h2x2 q = s4[k];
        float2 f0 = __half22float2(q.a);
        float2 f1 = __half22float2(q.b);
        sp += one_minus_erf(f0.x * c) + one_minus_erf(f0.y * c);
        sp += one_minus_erf(f1.x * c) + one_minus_erf(f1.y * c);
    }
    for (long long j = (m4 << 2) + tid; j < mloc; j += NTHR)
        sp += one_minus_erf(__half2float(s_d[j]) * c);

    block_reduce_1<NWARPS>(sp, &g_sum_p);

    // -------- block 0 finalizes --------
    __syncthreads();
    __threadfence();
    if (tid == 0) {
        if (bid != 0) {
            atomicAdd(&g_count, 1u);
        } else {
            const unsigned need = gridDim.x - 1;
            while (*((volatile unsigned*)&g_count) != need) { }
            g_count = 0;
            __threadfence();
            double mean_d = sdt / dn;
            float  p      = (float)(g_sum_p / dn);
            float  gamma  = -logf(p);
            float  pw     = expf(gamma * log1pf(-p));   // (1-p)^gamma
            out[0] = (float)mean_d * pw + log1pf((float)var);
            g_sum_d = 0.0; g_sum_d2 = 0.0; g_sum_p = 0.0;
        }
    }
}

// ============================ fallback path (large n) =======================
__global__ void afl_fb_pass1(const float* __restrict__ pred,
                             const float* __restrict__ target, long long n) {
    const long long n4 = n >> 2;
    const float4* __restrict__ p4 = (const float4*)pred;
    const float4* __restrict__ t4 = (const float4*)target;
    const long long stride = (long long)gridDim.x * blockDim.x;
    float sd = 0.0f, sd2 = 0.0f;
    for (long long i = (long long)blockIdx.x * blockDim.x + threadIdx.x; i < n4; i += stride) {
        float4 a = p4[i]; float4 b = t4[i];
        float d0 = fabsf(a.x - b.x), d1 = fabsf(a.y - b.y);
        float d2 = fabsf(a.z - b.z), d3 = fabsf(a.w - b.w);
        sd  += (d0 + d1) + (d2 + d3);
        sd2 += fmaf(d0, d0, d1 * d1) + fmaf(d2, d2, d3 * d3);
    }
    for (long long j = (n4 << 2) + (long long)blockIdx.x * blockDim.x + threadIdx.x;
         j < n; j += stride) {
        float d = fabsf(pred[j] - target[j]);
        sd += d; sd2 += d * d;
    }
    block_reduce_2<FB_WARPS>(sd, sd2, &g_sum_d, &g_sum_d2);
}

__global__ void afl_fb_pass2(const float* __restrict__ pred,
                             const float* __restrict__ target, long long n) {
    double sdt = g_sum_d, sd2t = g_sum_d2, dn = (double)n;
    double var = (sd2t - sdt * sdt / dn) / (dn - 1.0);
    float  c   = (float)(0.7071067811865476 / var);
    const long long n4 = n >> 2;
    const float4* __restrict__ p4 = (const float4*)pred;
    const float4* __restrict__ t4 = (const float4*)target;
    const long long stride = (long long)gridDim.x * blockDim.x;
    float sp = 0.0f;
    for (long long i = (long long)blockIdx.x * blockDim.x + threadIdx.x; i < n4; i += stride) {
        float4 a = p4[i]; float4 b = t4[i];
        sp += one_minus_erf(fabsf(a.x - b.x) * c) + one_minus_erf(fabsf(a.y - b.y) * c);
        sp += one_minus_erf(fabsf(a.z - b.z) * c) + one_minus_erf(fabsf(a.w - b.w) * c);
    }
    for (long long j = (n4 << 2) + (long long)blockIdx.x * blockDim.x + threadIdx.x;
         j < n; j += stride)
        sp += one_minus_erf(fabsf(pred[j] - target[j]) * c);
    block_reduce_1<FB_WARPS>(sp, &g_sum_p);
}

__global__ void afl_fb_finalize(float* __restrict__ out, long long n) {
    double dn = (double)n;
    double sdt = g_sum_d, sd2t = g_sum_d2;
    double mean_d = sdt / dn;
    double var = (sd2t - sdt * sdt / dn) / (dn - 1.0);
    float  p = (float)(g_sum_p / dn);
    float  gamma = -logf(p);
    float  pw = expf(gamma * log1pf(-p));
    out[0] = (float)mean_d * pw + log1pf((float)var);
    g_sum_d = 0.0; g_sum_d2 = 0.0; g_sum_p = 0.0;
}

// ================================ launcher ==================================
extern "C" void kernel_launch(void* const* d_in, const int* in_sizes, int n_in,
                              void* d_out, int out_size) {
    const float* pred   = (const float*)d_in[0];
    const float* target = (const float*)d_in[1];
    float* out = (float*)d_out;
    long long n = (long long)in_sizes[0];

    long long chunk = ((n + NBLK - 1) / NBLK + 3) & ~3LL;
    size_t smem = (size_t)chunk * sizeof(__half);

    if (smem <= 227 * 1024) {
        cudaFuncSetAttribute(afl_fused_kernel,
                             cudaFuncAttributeMaxDynamicSharedMemorySize,
                             (int)smem);
        afl_fused_kernel<<<NBLK, NTHR, smem>>>(pred, target, out, n, chunk);
    } else {
        afl_fb_pass1<<<FB_BLOCKS, FB_THREADS>>>(pred, target, n);
        afl_fb_pass2<<<FB_BLOCKS, FB_THREADS>>>(pred, target, n);
        afl_fb_finalize<<<1, 1>>>(out, n);
    }
}

// round 6
// speedup vs baseline: 1.3551x; 1.3551x over previous
#include <cuda_runtime.h>
#include <math.h>

// ---- persistent device state (no allocations allowed) ----
__device__ double   g_sum_d;
__device__ double   g_sum_d2;
__device__ double   g_sum_p;
__device__ unsigned g_count;    // grid-barrier arrive counter
__device__ unsigned g_gen;      // grid-barrier generation (monotonic across replays)

#define NBLK   148
#define NTHR   1024
#define NWARPS (NTHR / 32)

// fp32-bit log-binning: bin = float_bits(d) >> 17  (64 bins/octave).
// d < 16 => biased exp <= 130 => max bin 8383; 8448 covers with clamp.
#define NBINS  8448

__device__ __forceinline__ float warp_reduce_f(float v) {
    #pragma unroll
    for (int o = 16; o > 0; o >>= 1)
        v += __shfl_xor_sync(0xFFFFFFFFu, v, o);
    return v;
}

// 1 - erf(x), x >= 0. Abramowitz & Stegun 7.1.26, |err| <= 1.5e-7.
__device__ __forceinline__ float one_minus_erf(float x) {
    float t = __fdividef(1.0f, fmaf(0.3275911f, x, 1.0f));
    float poly = fmaf(t, 1.061405429f, -1.453152027f);
    poly = fmaf(poly, t, 1.421413741f);
    poly = fmaf(poly, t, -0.284496736f);
    poly = fmaf(poly, t, 0.254829592f);
    poly *= t;
    return poly * __expf(-x * x);
}

__device__ __forceinline__ void block_reduce_2(float sd, float sd2,
                                               double* out_a, double* out_b) {
    sd  = warp_reduce_f(sd);
    sd2 = warp_reduce_f(sd2);
    __shared__ double shA[NWARPS];
    __shared__ double shB[NWARPS];
    int lane = threadIdx.x & 31;
    int wid  = threadIdx.x >> 5;
    if (lane == 0) { shA[wid] = (double)sd; shB[wid] = (double)sd2; }
    __syncthreads();
    if (wid == 0) {
        double a = (lane < NWARPS) ? shA[lane] : 0.0;
        double b = (lane < NWARPS) ? shB[lane] : 0.0;
        #pragma unroll
        for (int o = 16; o > 0; o >>= 1) {
            a += __shfl_xor_sync(0xFFFFFFFFu, a, o);
            b += __shfl_xor_sync(0xFFFFFFFFu, b, o);
        }
        if (lane == 0) { atomicAdd(out_a, a); atomicAdd(out_b, b); }
    }
    __syncthreads();
}

__device__ __forceinline__ void block_reduce_1(float s, double* out) {
    s = warp_reduce_f(s);
    __shared__ double shC[NWARPS];
    int lane = threadIdx.x & 31;
    int wid  = threadIdx.x >> 5;
    if (lane == 0) shC[wid] = (double)s;
    __syncthreads();
    if (wid == 0) {
        double a = (lane < NWARPS) ? shC[lane] : 0.0;
        #pragma unroll
        for (int o = 16; o > 0; o >>= 1)
            a += __shfl_xor_sync(0xFFFFFFFFu, a, o);
        if (lane == 0) atomicAdd(out, a);
    }
}

// Sense-reversing grid barrier; all 148 blocks co-resident (1 per SM).
__device__ __forceinline__ void grid_barrier(unsigned nblocks) {
    __syncthreads();
    if (threadIdx.x == 0) {
        unsigned gen = *((volatile unsigned*)&g_gen);
        __threadfence();
        unsigned arrived = atomicAdd(&g_count, 1u);
        if (arrived == nblocks - 1) {
            g_count = 0;
            __threadfence();
            atomicAdd(&g_gen, 1u);
        } else {
            while (*((volatile unsigned*)&g_gen) == gen) { }
            __threadfence();
        }
    }
    __syncthreads();
}

// ============================ fused persistent kernel =======================
__global__ __launch_bounds__(NTHR, 1)
void afl_fused_kernel(const float* __restrict__ pred,
                      const float* __restrict__ target,
                      float* __restrict__ out,
                      long long n, long long chunk /* multiple of 4 */) {
    __shared__ unsigned s_hist[NBINS];

    const int tid = threadIdx.x;
    const int bid = blockIdx.x;

    // zero histogram (fresh each launch / graph replay)
    for (int b = tid; b < NBINS; b += NTHR) s_hist[b] = 0u;
    __syncthreads();

    long long bstart = (long long)bid * chunk;
    if (bstart > n) bstart = n;
    long long bend = bstart + chunk;
    if (bend > n) bend = n;

    const long long b4s = bstart >> 2;
    const long long b4e = bend >> 2;

    const float4* __restrict__ p4 = (const float4*)pred;
    const float4* __restrict__ t4 = (const float4*)target;

    // -------- pass 1: sum d, sum d^2, histogram d by fp32 bit pattern --------
    float sd = 0.0f, sd2 = 0.0f;
    long long i = b4s + tid;
    for (; i + 3LL * NTHR < b4e; i += 4LL * NTHR) {
        float4 av[4], bv[4];
        #pragma unroll
        for (int u = 0; u < 4; u++) av[u] = __ldcs(&p4[i + (long long)u * NTHR]);
        #pragma unroll
        for (int u = 0; u < 4; u++) bv[u] = __ldcs(&t4[i + (long long)u * NTHR]);
        #pragma unroll
        for (int u = 0; u < 4; u++) {
            float d0 = fabsf(av[u].x - bv[u].x);
            float d1 = fabsf(av[u].y - bv[u].y);
            float d2 = fabsf(av[u].z - bv[u].z);
            float d3 = fabsf(av[u].w - bv[u].w);
            sd  += (d0 + d1) + (d2 + d3);
            sd2 += fmaf(d0, d0, d1 * d1) + fmaf(d2, d2, d3 * d3);
            unsigned c0 = min(__float_as_uint(d0) >> 17, NBINS - 1u);
            unsigned c1 = min(__float_as_uint(d1) >> 17, NBINS - 1u);
            unsigned c2 = min(__float_as_uint(d2) >> 17, NBINS - 1u);
            unsigned c3 = min(__float_as_uint(d3) >> 17, NBINS - 1u);
            atomicAdd(&s_hist[c0], 1u);
            atomicAdd(&s_hist[c1], 1u);
            atomicAdd(&s_hist[c2], 1u);
            atomicAdd(&s_hist[c3], 1u);
        }
    }
    for (; i < b4e; i += NTHR) {
        float4 a = __ldcs(&p4[i]);
        float4 b = __ldcs(&t4[i]);
        float d0 = fabsf(a.x - b.x);
        float d1 = fabsf(a.y - b.y);
        float d2 = fabsf(a.z - b.z);
        float d3 = fabsf(a.w - b.w);
        sd  += (d0 + d1) + (d2 + d3);
        sd2 += fmaf(d0, d0, d1 * d1) + fmaf(d2, d2, d3 * d3);
        atomicAdd(&s_hist[min(__float_as_uint(d0) >> 17, NBINS - 1u)], 1u);
        atomicAdd(&s_hist[min(__float_as_uint(d1) >> 17, NBINS - 1u)], 1u);
        atomicAdd(&s_hist[min(__float_as_uint(d2) >> 17, NBINS - 1u)], 1u);
        atomicAdd(&s_hist[min(__float_as_uint(d3) >> 17, NBINS - 1u)], 1u);
    }
    for (long long j = (b4e << 2) + tid; j < bend; j += NTHR) {  // n%4 tail
        float d = fabsf(pred[j] - target[j]);
        sd += d; sd2 += d * d;
        atomicAdd(&s_hist[min(__float_as_uint(d) >> 17, NBINS - 1u)], 1u);
    }

    block_reduce_2(sd, sd2, &g_sum_d, &g_sum_d2);
    __threadfence();
    grid_barrier(gridDim.x);

    // -------- var is now global-complete --------
    const double sdt  = g_sum_d;
    const double sd2t = g_sum_d2;
    const double dn   = (double)n;
    const double var  = (sd2t - sdt * sdt / dn) / (dn - 1.0);
    const float  c    = (float)(0.7071067811865476 / var);

    // -------- pass 2: evaluate erf once per populated histogram bin ---------
    // Within a bin, value is LINEAR in bits (same exponent region), so the
    // bit-midpoint 0x10000 is the exact value-midpoint: first-order exact.
    float sp = 0.0f;
    for (int b = tid; b < NBINS; b += NTHR) {
        unsigned cnt = s_hist[b];
        if (cnt) {
            float rep = __uint_as_float(((unsigned)b << 17) | 0x10000u);
            sp += (float)cnt * one_minus_erf(rep * c);
        }
    }

    block_reduce_1(sp, &g_sum_p);

    // -------- phase-2 arrive; block 0 finalizes --------
    __syncthreads();
    __threadfence();
    if (tid == 0) {
        if (bid != 0) {
            atomicAdd(&g_count, 1u);
        } else {
            const unsigned need = gridDim.x - 1;
            while (*((volatile unsigned*)&g_count) != need) { }
            g_count = 0;
            __threadfence();
            double mean_d = sdt / dn;
            float  p      = (float)(g_sum_p / dn);
            float  gamma  = -logf(p);
            float  pw     = expf(gamma * log1pf(-p));   // (1-p)^gamma
            out[0] = (float)mean_d * pw + log1pf((float)var);
            g_sum_d = 0.0; g_sum_d2 = 0.0; g_sum_p = 0.0;
        }
    }
}

// ================================ launcher ==================================
extern "C" void kernel_launch(void* const* d_in, const int* in_sizes, int n_in,
                              void* d_out, int out_size) {
    const float* pred   = (const float*)d_in[0];
    const float* target = (const float*)d_in[1];
    float* out = (float*)d_out;
    long long n = (long long)in_sizes[0];

    long long chunk = ((n + NBLK - 1) / NBLK + 3) & ~3LL;   // per-block elems, mult of 4
    afl_fused_kernel<<<NBLK, NTHR>>>(pred, target, out, n, chunk);
}